// round 4
// baseline (speedup 1.0000x reference)
#include <cuda_runtime.h>
#include <mma.h>
#include <cstdint>

using namespace nvcuda;

// Problem dims (fixed)
#define BATCH 8
#define NQ    2048
#define NKV   2048
#define DQ    1024
#define DKV   1024
#define HH    256

// GEMM tile config: CTA tile 128x64, 8 warps as 4x2 (warp tile 32x32)
#define BM 128
#define BN 64
#define BKC 32
#define NTHREADS 256

// Scratch (device globals — no allocation allowed)
__device__ float g_sigQ[BATCH * NQ * HH];   // sigmoid(Q)
__device__ float g_expK[BATCH * NKV * HH];  // exp(K)   tf32-rounded, row-major [B*NKV, H]
__device__ float g_ekv [BATCH * NKV * HH];  // exp(K)*V tf32-rounded, row-major [B*NKV, H]
__device__ float g_Yt  [BATCH * NQ * HH];   // sig(Q)*num/den

// smem layout (floats)
#define SA_STRIDE 36
#define SB_STRIDE 68
#define SA_TILE  (BM * SA_STRIDE)          // 4608 floats
#define SB_TILE  (BKC * SB_STRIDE)         // 2176 floats
#define SA_OFF(buf)    ((buf) * SA_TILE)
#define SB_OFF(t, buf) (2 * SA_TILE + ((t) * 2 + (buf)) * SB_TILE)
#define SMEM_FLOATS(NB) (2 * SA_TILE + (NB) * 2 * SB_TILE)
// epilogue staging: per-warp 32 x 36 floats (reuses mainloop smem)
#define STG_STRIDE 36
#define STG_WARP  (32 * STG_STRIDE)

__device__ __forceinline__ void cp16(uint32_t saddr, const void* gptr) {
    asm volatile("cp.async.cg.shared.global [%0], [%1], 16;" :: "r"(saddr), "l"(gptr));
}
#define CP_COMMIT() asm volatile("cp.async.commit_group;" ::: "memory")

__device__ __forceinline__ float to_tf32(float x) {
    float r;
    asm("cvt.rna.tf32.f32 %0, %1;" : "=f"(r) : "f"(x));
    return r;
}

// ---------------------------------------------------------------------------
// Unified tf32 wmma GEMM (row-major A, row-major B), single or dual B.
// EPI: 0 = O0 = sigmoid(A@B0 + v0)
//      1 = ek=exp(A@B0+v0); O0=tf32(ek); O1=tf32(ek*(A@B1+v1))
//      2 = O0 = aux * (A@B0) / (A@B1)
//      3 = O0 = A@B0 + v0
// CVT:  convert fragments to tf32 after load (false when operands pre-rounded)
// EXPA: apply tf32(exp(.)) to the A tile in smem after arrival (AFT core: A=bias)
// ---------------------------------------------------------------------------
template<int NB, int EPI, bool CVT, bool EXPA>
__global__ __launch_bounds__(NTHREADS, 2) void gemm_tc_kernel(
    const float* __restrict__ A, unsigned long long strideAz, int lda,
    const float* __restrict__ B0g, const float* __restrict__ B1g,
    unsigned long long strideBz, int Ktot,
    const float* __restrict__ v0, const float* __restrict__ v1,
    const float* __restrict__ aux, unsigned long long strideXz,
    float* __restrict__ O0, float* __restrict__ O1, unsigned long long strideOz)
{
    extern __shared__ __align__(16) float sm[];
    const int tid  = threadIdx.x;
    const int wid  = tid >> 5;
    const int lane = tid & 31;
    const int m0 = blockIdx.x * BM;
    const int n0 = blockIdx.y * BN;
    const int z  = blockIdx.z;
    const int wm = wid >> 1;      // 0..3
    const int wn = wid & 1;       // 0..1

    const float* Ab = A + (size_t)z * strideAz + (size_t)m0 * lda;
    const float* Bb[2];
    Bb[0] = B0g + (size_t)z * strideBz;
    if (NB > 1) Bb[1] = B1g + (size_t)z * strideBz;

    using FragA = wmma::fragment<wmma::matrix_a, 16, 16, 8, wmma::precision::tf32, wmma::row_major>;
    using FragB = wmma::fragment<wmma::matrix_b, 16, 16, 8, wmma::precision::tf32, wmma::row_major>;
    using FragC = wmma::fragment<wmma::accumulator, 16, 16, 8, float>;

    FragC acc[NB][2][2];
#pragma unroll
    for (int t = 0; t < NB; t++)
#pragma unroll
        for (int mi = 0; mi < 2; mi++)
#pragma unroll
            for (int ni = 0; ni < 2; ni++)
                wmma::fill_fragment(acc[t][mi][ni], 0.0f);

    auto load_chunk = [&](int buf, int k0) {
        // A tile: 128 x 32 floats = 1024 float4, 4 per thread
#pragma unroll
        for (int i = 0; i < 4; i++) {
            int idx = tid + i * 256;
            int r = idx >> 3, c4 = idx & 7;
            uint32_t s = (uint32_t)__cvta_generic_to_shared(
                sm + SA_OFF(buf) + r * SA_STRIDE + c4 * 4);
            cp16(s, Ab + (size_t)r * lda + k0 + c4 * 4);
        }
        // B tiles: 32 x 64 floats each = 512 float4, 2 per thread
#pragma unroll
        for (int t = 0; t < NB; t++)
#pragma unroll
            for (int i = 0; i < 2; i++) {
                int idx = tid + i * 256;
                int r = idx >> 4, c4 = idx & 15;
                uint32_t s = (uint32_t)__cvta_generic_to_shared(
                    sm + SB_OFF(t, buf) + r * SB_STRIDE + c4 * 4);
                cp16(s, Bb[t] + (size_t)(k0 + r) * HH + n0 + c4 * 4);
            }
        CP_COMMIT();
    };

    load_chunk(0, 0);
    const int nchunk = Ktot / BKC;

    for (int c = 0; c < nchunk; c++) {
        const int buf = c & 1;
        if (c + 1 < nchunk) {
            load_chunk(buf ^ 1, (c + 1) * BKC);
            asm volatile("cp.async.wait_group 1;" ::: "memory");
        } else {
            asm volatile("cp.async.wait_group 0;" ::: "memory");
        }
        __syncthreads();

        if (EXPA) {
            // In-place transform of the A tile: a = tf32(exp(a))
#pragma unroll
            for (int i = 0; i < 4; i++) {
                int idx = tid + i * 256;
                int r = idx >> 3, c4 = idx & 7;
                float4* p = reinterpret_cast<float4*>(sm + SA_OFF(buf) + r * SA_STRIDE + c4 * 4);
                float4 v = *p;
                v.x = to_tf32(__expf(v.x));
                v.y = to_tf32(__expf(v.y));
                v.z = to_tf32(__expf(v.z));
                v.w = to_tf32(__expf(v.w));
                *p = v;
            }
            __syncthreads();
        }

#pragma unroll
        for (int kk = 0; kk < 4; kk++) {
            FragA a[2];
#pragma unroll
            for (int mi = 0; mi < 2; mi++) {
                wmma::load_matrix_sync(a[mi],
                    sm + SA_OFF(buf) + (wm * 32 + mi * 16) * SA_STRIDE + kk * 8, SA_STRIDE);
                if (CVT) {
#pragma unroll
                    for (int e = 0; e < a[mi].num_elements; e++)
                        a[mi].x[e] = wmma::__float_to_tf32(a[mi].x[e]);
                }
            }
#pragma unroll
            for (int t = 0; t < NB; t++) {
#pragma unroll
                for (int ni = 0; ni < 2; ni++) {
                    FragB b;
                    wmma::load_matrix_sync(b,
                        sm + SB_OFF(t, buf) + kk * 8 * SB_STRIDE + wn * 32 + ni * 16, SB_STRIDE);
                    if (CVT) {
#pragma unroll
                        for (int e = 0; e < b.num_elements; e++)
                            b.x[e] = wmma::__float_to_tf32(b.x[e]);
                    }
#pragma unroll
                    for (int mi = 0; mi < 2; mi++)
                        wmma::mma_sync(acc[t][mi][ni], a[mi], b, acc[t][mi][ni]);
                }
            }
        }
        __syncthreads();
    }

    // ------------------- Epilogue (per-warp smem staging) --------------------
    float* stage = sm + wid * STG_WARP;

    float r0[32], r1[32];
#pragma unroll
    for (int t = 0; t < NB; t++) {
        __syncwarp();
#pragma unroll
        for (int mi = 0; mi < 2; mi++)
#pragma unroll
            for (int ni = 0; ni < 2; ni++)
                wmma::store_matrix_sync(stage + mi * 16 * STG_STRIDE + ni * 16,
                                        acc[t][mi][ni], STG_STRIDE, wmma::mem_row_major);
        __syncwarp();
        float* dst = (t == 0) ? r0 : r1;
#pragma unroll
        for (int c4 = 0; c4 < 8; c4++) {
            float4 v = *reinterpret_cast<float4*>(stage + lane * STG_STRIDE + c4 * 4);
            dst[c4 * 4 + 0] = v.x; dst[c4 * 4 + 1] = v.y;
            dst[c4 * 4 + 2] = v.z; dst[c4 * 4 + 3] = v.w;
        }
    }

    const int grow = m0 + wm * 32 + lane;
    const int gcolb = n0 + wn * 32;
    const size_t obase = (size_t)z * strideOz + (size_t)grow * HH + gcolb;

#pragma unroll
    for (int c4 = 0; c4 < 8; c4++) {
        int gcol = gcolb + c4 * 4;
        if (EPI == 0) {         // sigmoid(x + bias)
            float4 bv = *reinterpret_cast<const float4*>(v0 + gcol);
            float4 ov;
            ov.x = 1.0f / (1.0f + __expf(-(r0[c4 * 4 + 0] + bv.x)));
            ov.y = 1.0f / (1.0f + __expf(-(r0[c4 * 4 + 1] + bv.y)));
            ov.z = 1.0f / (1.0f + __expf(-(r0[c4 * 4 + 2] + bv.z)));
            ov.w = 1.0f / (1.0f + __expf(-(r0[c4 * 4 + 3] + bv.w)));
            *reinterpret_cast<float4*>(O0 + obase + c4 * 4) = ov;
        } else if (EPI == 1) {  // expK / ekv (tf32-rounded for the AFT core)
            float4 bk = *reinterpret_cast<const float4*>(v0 + gcol);
            float4 bb = *reinterpret_cast<const float4*>(v1 + gcol);
            float ekx = __expf(r0[c4 * 4 + 0] + bk.x);
            float eky = __expf(r0[c4 * 4 + 1] + bk.y);
            float ekz = __expf(r0[c4 * 4 + 2] + bk.z);
            float ekw = __expf(r0[c4 * 4 + 3] + bk.w);
            float4 ek, kv;
            ek.x = to_tf32(ekx); kv.x = to_tf32(ekx * (r1[c4 * 4 + 0] + bb.x));
            ek.y = to_tf32(eky); kv.y = to_tf32(eky * (r1[c4 * 4 + 1] + bb.y));
            ek.z = to_tf32(ekz); kv.z = to_tf32(ekz * (r1[c4 * 4 + 2] + bb.z));
            ek.w = to_tf32(ekw); kv.w = to_tf32(ekw * (r1[c4 * 4 + 3] + bb.w));
            *reinterpret_cast<float4*>(O0 + obase + c4 * 4) = ek;
            *reinterpret_cast<float4*>(O1 + obase + c4 * 4) = kv;
        } else if (EPI == 2) {  // Yt = sigQ * num / den
            float4 sq = *reinterpret_cast<const float4*>(
                aux + (size_t)z * strideXz + (size_t)grow * HH + gcol);
            float4 ov;
            ov.x = sq.x * __fdividef(r0[c4 * 4 + 0], r1[c4 * 4 + 0]);
            ov.y = sq.y * __fdividef(r0[c4 * 4 + 1], r1[c4 * 4 + 1]);
            ov.z = sq.z * __fdividef(r0[c4 * 4 + 2], r1[c4 * 4 + 2]);
            ov.w = sq.w * __fdividef(r0[c4 * 4 + 3], r1[c4 * 4 + 3]);
            *reinterpret_cast<float4*>(O0 + obase + c4 * 4) = ov;
        } else {                // out = x + bias
            float4 bv = *reinterpret_cast<const float4*>(v0 + gcol);
            float4 ov;
            ov.x = r0[c4 * 4 + 0] + bv.x;
            ov.y = r0[c4 * 4 + 1] + bv.y;
            ov.z = r0[c4 * 4 + 2] + bv.z;
            ov.w = r0[c4 * 4 + 3] + bv.w;
            *reinterpret_cast<float4*>(O0 + obase + c4 * 4) = ov;
        }
    }
}

// ---------------------------------------------------------------------------
// Launch.  Inputs (metadata order):
//  0:x_q 1:x_kv 2:bias 3:wq_w 4:wq_b 5:wk_w 6:wk_b 7:wv_w 8:wv_b 9:f2_w 10:f2_b
// ---------------------------------------------------------------------------
extern "C" void kernel_launch(void* const* d_in, const int* in_sizes, int n_in,
                              void* d_out, int out_size) {
    (void)in_sizes; (void)n_in; (void)out_size;
    const float* x_q  = (const float*)d_in[0];
    const float* x_kv = (const float*)d_in[1];
    const float* bias = (const float*)d_in[2];
    const float* wq_w = (const float*)d_in[3];
    const float* wq_b = (const float*)d_in[4];
    const float* wk_w = (const float*)d_in[5];
    const float* wk_b = (const float*)d_in[6];
    const float* wv_w = (const float*)d_in[7];
    const float* wv_b = (const float*)d_in[8];
    const float* f2_w = (const float*)d_in[9];
    const float* f2_b = (const float*)d_in[10];
    float* out = (float*)d_out;

    float *p_sigQ, *p_expK, *p_ekv, *p_Yt;
    cudaGetSymbolAddress((void**)&p_sigQ, g_sigQ);
    cudaGetSymbolAddress((void**)&p_expK, g_expK);
    cudaGetSymbolAddress((void**)&p_ekv,  g_ekv);
    cudaGetSymbolAddress((void**)&p_Yt,   g_Yt);

    const int smem1 = SMEM_FLOATS(1) * 4;   // 54272 B
    const int smem2 = SMEM_FLOATS(2) * 4;   // 71680 B
    cudaFuncSetAttribute((const void*)gemm_tc_kernel<1, 0, true, false>,
                         cudaFuncAttributeMaxDynamicSharedMemorySize, smem1);
    cudaFuncSetAttribute((const void*)gemm_tc_kernel<2, 1, true, false>,
                         cudaFuncAttributeMaxDynamicSharedMemorySize, smem2);
    cudaFuncSetAttribute((const void*)gemm_tc_kernel<2, 2, false, true>,
                         cudaFuncAttributeMaxDynamicSharedMemorySize, smem2);
    cudaFuncSetAttribute((const void*)gemm_tc_kernel<1, 3, true, false>,
                         cudaFuncAttributeMaxDynamicSharedMemorySize, smem1);

    // 1) sigQ = sigmoid(x_q @ wq_w + wq_b)
    {
        dim3 grid((BATCH * NQ) / BM, HH / BN, 1);
        gemm_tc_kernel<1, 0, true, false><<<grid, NTHREADS, smem1>>>(
            x_q, 0ull, DQ, wq_w, nullptr, 0ull, DQ,
            wq_b, nullptr, nullptr, 0ull, p_sigQ, nullptr, 0ull);
    }
    // 2) expK = tf32(exp(x_kv@wk+bk)); ekv = tf32(expK*(x_kv@wv+bv))
    {
        dim3 grid((BATCH * NKV) / BM, HH / BN, 1);
        gemm_tc_kernel<2, 1, true, false><<<grid, NTHREADS, smem2>>>(
            x_kv, 0ull, DKV, wk_w, wv_w, 0ull, DKV,
            wk_b, wv_b, nullptr, 0ull, p_expK, p_ekv, 0ull);
    }
    // 3) Yt = sigQ * (exp(bias)@ekv) / (exp(bias)@expK), batched over z
    //    (exp applied to the A tile in smem; operands pre-rounded -> CVT off)
    {
        dim3 grid(NQ / BM, HH / BN, BATCH);
        gemm_tc_kernel<2, 2, false, true><<<grid, NTHREADS, smem2>>>(
            bias, (unsigned long long)NQ * NKV, NKV,
            p_ekv, p_expK, (unsigned long long)NKV * HH, NKV,
            nullptr, nullptr, p_sigQ, (unsigned long long)NQ * HH,
            p_Yt, nullptr, (unsigned long long)NQ * HH);
    }
    // 4) out = Yt @ f2_w + f2_b
    {
        dim3 grid((BATCH * NQ) / BM, HH / BN, 1);
        gemm_tc_kernel<1, 3, true, false><<<grid, NTHREADS, smem1>>>(
            p_Yt, 0ull, HH, f2_w, nullptr, 0ull, HH,
            f2_b, nullptr, nullptr, 0ull, out, nullptr, 0ull);
    }
}

// round 5
// speedup vs baseline: 1.6755x; 1.6755x over previous
#include <cuda_runtime.h>
#include <cuda_fp16.h>
#include <mma.h>
#include <cstdint>

using namespace nvcuda;

// Problem dims (fixed)
#define BATCH 8
#define NQ    2048
#define NKV   2048
#define DQ    1024
#define DKV   1024
#define HH    256
#define NI    512            // interleaved (num,den) width

// Scratch (device globals — no allocation allowed)
__device__ __half g_expwh[(size_t)BATCH * NQ * NKV]; // fp16 exp(bias)      67 MB
__device__ __half g_kvi [BATCH * NKV * NI];          // interleaved ekv/expK 16.8 MB
__device__ float  g_wkv [DKV * NI];                  // interleaved wk|wv    2 MB
__device__ float  g_sigQ[BATCH * NQ * HH];           // sigmoid(Q)          16.8 MB
__device__ float  g_Yt  [BATCH * NQ * HH];           // sig(Q)*num/den      16.8 MB

__device__ __forceinline__ void cp16(uint32_t saddr, const void* gptr) {
    asm volatile("cp.async.cg.shared.global [%0], [%1], 16;" :: "r"(saddr), "l"(gptr));
}
#define CP_COMMIT() asm volatile("cp.async.commit_group;" ::: "memory")
#define CP_WAIT1()  asm volatile("cp.async.wait_group 1;" ::: "memory")
#define CP_WAIT0()  asm volatile("cp.async.wait_group 0;" ::: "memory")

// ---------------------------------------------------------------------------
// Prep: interleave wk|wv columns -> g_wkv [DKV x 512], col 2j=wk_j, 2j+1=wv_j
// ---------------------------------------------------------------------------
__global__ __launch_bounds__(256) void prep_wkv_kernel(
    const float* __restrict__ wk, const float* __restrict__ wv)
{
    int idx = blockIdx.x * 256 + threadIdx.x;   // k*256 + j
    reinterpret_cast<float2*>(g_wkv)[idx] = make_float2(wk[idx], wv[idx]);
}

// ---------------------------------------------------------------------------
// exp(bias) -> fp16
// ---------------------------------------------------------------------------
__global__ __launch_bounds__(256) void exp_bias_h_kernel(const float* __restrict__ bias) {
    size_t i = (size_t)blockIdx.x * 256 + threadIdx.x;  // 8 elems per thread
    float4 a = reinterpret_cast<const float4*>(bias)[2 * i];
    float4 b = reinterpret_cast<const float4*>(bias)[2 * i + 1];
    __half2 h[4];
    h[0] = __floats2half2_rn(__expf(a.x), __expf(a.y));
    h[1] = __floats2half2_rn(__expf(a.z), __expf(a.w));
    h[2] = __floats2half2_rn(__expf(b.x), __expf(b.y));
    h[3] = __floats2half2_rn(__expf(b.z), __expf(b.w));
    reinterpret_cast<uint4*>(g_expwh)[i] = *reinterpret_cast<uint4*>(h);
}

// ===========================================================================
// tf32 GEMM, BM=128 BN=128 BK=32, 8 warps (4x2), warp tile 32x64,
// 3-stage cp.async pipeline. Row-major A [M,K], row-major B [K,N].
// EPI: 0 = Of = sigmoid(x + v0)         (ldo cols)
//      1 = pairwise (K,V) epilogue -> Oh interleaved fp16 (ekv, expK)
//      2 = Of = x + v0
// ===========================================================================
#define SA_STRIDE 36
#define SB_STRIDE 136
#define STAGE_F   (128 * SA_STRIDE + 32 * SB_STRIDE)   // 8960 floats
#define SMEM32    (3 * STAGE_F * 4)                    // 107520 B
#define STG_STRIDE 68
#define STG_WARP   (32 * STG_STRIDE)

template<int EPI>
__global__ __launch_bounds__(256) void gemm32_kernel(
    const float* __restrict__ A, int lda,
    const float* __restrict__ Bg, int ldb, int Ktot,
    const float* __restrict__ v0, const float* __restrict__ v1,
    float* __restrict__ Of, __half* __restrict__ Oh, int ldo)
{
    extern __shared__ __align__(16) float sm[];
    const int tid = threadIdx.x, wid = tid >> 5, lane = tid & 31;
    const int m0 = blockIdx.x * 128, n0 = blockIdx.y * 128;
    const int wm = wid >> 1, wn = wid & 1;
    const float* Ab = A + (size_t)m0 * lda;

    using FA = wmma::fragment<wmma::matrix_a, 16, 16, 8, wmma::precision::tf32, wmma::row_major>;
    using FB = wmma::fragment<wmma::matrix_b, 16, 16, 8, wmma::precision::tf32, wmma::row_major>;
    using FC = wmma::fragment<wmma::accumulator, 16, 16, 8, float>;

    FC acc[2][4];
#pragma unroll
    for (int mi = 0; mi < 2; mi++)
#pragma unroll
        for (int ni = 0; ni < 4; ni++)
            wmma::fill_fragment(acc[mi][ni], 0.0f);

    auto load = [&](int c) {
        float* base = sm + (c % 3) * STAGE_F;
        const int k0 = c * 32;
#pragma unroll
        for (int i = 0; i < 4; i++) {       // A: 128x32
            int idx = tid + i * 256;
            int r = idx >> 3, c4 = idx & 7;
            cp16((uint32_t)__cvta_generic_to_shared(base + r * SA_STRIDE + c4 * 4),
                 Ab + (size_t)r * lda + k0 + c4 * 4);
        }
#pragma unroll
        for (int i = 0; i < 4; i++) {       // B: 32x128
            int idx = tid + i * 256;
            int r = idx >> 5, c4 = idx & 31;
            cp16((uint32_t)__cvta_generic_to_shared(
                     base + 128 * SA_STRIDE + r * SB_STRIDE + c4 * 4),
                 Bg + (size_t)(k0 + r) * ldb + n0 + c4 * 4);
        }
        CP_COMMIT();
    };

    const int nchunk = Ktot / 32;
    load(0);
    if (nchunk > 1) load(1);

    for (int c = 0; c < nchunk; c++) {
        if (c + 1 < nchunk) CP_WAIT1(); else CP_WAIT0();
        __syncthreads();
        if (c + 2 < nchunk) load(c + 2);

        float* Abase = sm + (c % 3) * STAGE_F;
        float* Bbase = Abase + 128 * SA_STRIDE;
#pragma unroll
        for (int kk = 0; kk < 4; kk++) {
            FA a[2];
#pragma unroll
            for (int mi = 0; mi < 2; mi++) {
                wmma::load_matrix_sync(a[mi],
                    Abase + (wm * 32 + mi * 16) * SA_STRIDE + kk * 8, SA_STRIDE);
#pragma unroll
                for (int e = 0; e < a[mi].num_elements; e++)
                    a[mi].x[e] = wmma::__float_to_tf32(a[mi].x[e]);
            }
#pragma unroll
            for (int ni = 0; ni < 4; ni++) {
                FB b;
                wmma::load_matrix_sync(b,
                    Bbase + kk * 8 * SB_STRIDE + wn * 64 + ni * 16, SB_STRIDE);
#pragma unroll
                for (int e = 0; e < b.num_elements; e++)
                    b.x[e] = wmma::__float_to_tf32(b.x[e]);
#pragma unroll
                for (int mi = 0; mi < 2; mi++)
                    wmma::mma_sync(acc[mi][ni], a[mi], b, acc[mi][ni]);
            }
        }
    }

    // ---- Epilogue: per-warp smem staging ----
    __syncthreads();
    float* stage = sm + wid * STG_WARP;
#pragma unroll
    for (int mi = 0; mi < 2; mi++)
#pragma unroll
        for (int ni = 0; ni < 4; ni++)
            wmma::store_matrix_sync(stage + mi * 16 * STG_STRIDE + ni * 16,
                                    acc[mi][ni], STG_STRIDE, wmma::mem_row_major);
    __syncwarp();

    const int grow  = m0 + wm * 32 + lane;
    const int gcolb = n0 + wn * 64;

#pragma unroll
    for (int c4 = 0; c4 < 16; c4++) {
        float4 v = *reinterpret_cast<float4*>(stage + lane * STG_STRIDE + c4 * 4);
        int gc = gcolb + c4 * 4;
        if (EPI == 0) {
            float4 bv = *reinterpret_cast<const float4*>(v0 + gc);
            float4 ov;
            ov.x = 1.0f / (1.0f + __expf(-(v.x + bv.x)));
            ov.y = 1.0f / (1.0f + __expf(-(v.y + bv.y)));
            ov.z = 1.0f / (1.0f + __expf(-(v.z + bv.z)));
            ov.w = 1.0f / (1.0f + __expf(-(v.w + bv.w)));
            *reinterpret_cast<float4*>(Of + (size_t)grow * ldo + gc) = ov;
        } else if (EPI == 1) {
            // pairs: (v.x=K, v.y=V) at j=gc/2; (v.z=K, v.w=V) at j+1
            int j = gc >> 1;
            float ek0 = __expf(v.x + v0[j]);
            float kv0 = ek0 * (v.y + v1[j]);
            float ek1 = __expf(v.z + v0[j + 1]);
            float kv1 = ek1 * (v.w + v1[j + 1]);
            __half2* po = reinterpret_cast<__half2*>(Oh + (size_t)grow * ldo + gc);
            po[0] = __floats2half2_rn(kv0, ek0);   // cols (2j, 2j+1)
            po[1] = __floats2half2_rn(kv1, ek1);
        } else {
            float4 bv = *reinterpret_cast<const float4*>(v0 + gc);
            float4 ov;
            ov.x = v.x + bv.x; ov.y = v.y + bv.y;
            ov.z = v.z + bv.z; ov.w = v.w + bv.w;
            *reinterpret_cast<float4*>(Of + (size_t)grow * ldo + gc) = ov;
        }
    }
}

// ===========================================================================
// AFT core: fp16 GEMM  A=exp(bias) [NQ,NKV]  B=kvi [NKV,512] per batch.
// BM=128 BN=128 BK=64, m16n16k16, 3-stage pipeline.
// Epilogue: Yt[h] = sigQ[h] * num/den from adjacent (even,odd) columns.
// ===========================================================================
#define HA_STRIDE 72
#define HB_STRIDE 136
#define HSTAGE    (128 * HA_STRIDE + 64 * HB_STRIDE)   // 17920 halves
#define SMEM16    (3 * HSTAGE * 2)                     // 107520 B

__global__ __launch_bounds__(256) void aft16_kernel() {
    extern __shared__ __align__(16) float smf[];
    __half* sm = reinterpret_cast<__half*>(smf);
    const int tid = threadIdx.x, wid = tid >> 5, lane = tid & 31;
    const int m0 = blockIdx.x * 128, n0 = blockIdx.y * 128;
    const int z = blockIdx.z;
    const int wm = wid >> 1, wn = wid & 1;

    const __half* Ab = g_expwh + (size_t)z * NQ * NKV + (size_t)m0 * NKV;
    const __half* Bb = g_kvi + (size_t)z * NKV * NI;

    using FA = wmma::fragment<wmma::matrix_a, 16, 16, 16, __half, wmma::row_major>;
    using FB = wmma::fragment<wmma::matrix_b, 16, 16, 16, __half, wmma::row_major>;
    using FC = wmma::fragment<wmma::accumulator, 16, 16, 16, float>;

    FC acc[2][4];
#pragma unroll
    for (int mi = 0; mi < 2; mi++)
#pragma unroll
        for (int ni = 0; ni < 4; ni++)
            wmma::fill_fragment(acc[mi][ni], 0.0f);

    auto load = [&](int c) {
        __half* base = sm + (c % 3) * HSTAGE;
        const int k0 = c * 64;
#pragma unroll
        for (int i = 0; i < 4; i++) {       // A: 128x64 halves
            int idx = tid + i * 256;
            int r = idx >> 3, c8 = idx & 7;
            cp16((uint32_t)__cvta_generic_to_shared(base + r * HA_STRIDE + c8 * 8),
                 Ab + (size_t)r * NKV + k0 + c8 * 8);
        }
#pragma unroll
        for (int i = 0; i < 4; i++) {       // B: 64x128 halves
            int idx = tid + i * 256;
            int r = idx >> 4, c8 = idx & 15;
            cp16((uint32_t)__cvta_generic_to_shared(
                     base + 128 * HA_STRIDE + r * HB_STRIDE + c8 * 8),
                 Bb + (size_t)(k0 + r) * NI + n0 + c8 * 8);
        }
        CP_COMMIT();
    };

    const int nchunk = NKV / 64;   // 32
    load(0);
    load(1);

    for (int c = 0; c < nchunk; c++) {
        if (c + 1 < nchunk) CP_WAIT1(); else CP_WAIT0();
        __syncthreads();
        if (c + 2 < nchunk) load(c + 2);

        __half* Abase = sm + (c % 3) * HSTAGE;
        __half* Bbase = Abase + 128 * HA_STRIDE;
#pragma unroll
        for (int kk = 0; kk < 4; kk++) {
            FA a[2];
#pragma unroll
            for (int mi = 0; mi < 2; mi++)
                wmma::load_matrix_sync(a[mi],
                    Abase + (wm * 32 + mi * 16) * HA_STRIDE + kk * 16, HA_STRIDE);
#pragma unroll
            for (int ni = 0; ni < 4; ni++) {
                FB b;
                wmma::load_matrix_sync(b,
                    Bbase + kk * 16 * HB_STRIDE + wn * 64 + ni * 16, HB_STRIDE);
#pragma unroll
                for (int mi = 0; mi < 2; mi++)
                    wmma::mma_sync(acc[mi][ni], a[mi], b, acc[mi][ni]);
            }
        }
    }

    // ---- Epilogue ----
    __syncthreads();
    float* stage = smf + wid * STG_WARP;
#pragma unroll
    for (int mi = 0; mi < 2; mi++)
#pragma unroll
        for (int ni = 0; ni < 4; ni++)
            wmma::store_matrix_sync(stage + mi * 16 * STG_STRIDE + ni * 16,
                                    acc[mi][ni], STG_STRIDE, wmma::mem_row_major);
    __syncwarp();

    const int grow = m0 + wm * 32 + lane;
    const int hb = (n0 + wn * 64) >> 1;      // 32 h values per thread
    const size_t sqbase = (size_t)z * NQ * HH + (size_t)grow * HH + hb;

    float yt[32];
#pragma unroll
    for (int c4 = 0; c4 < 16; c4++) {
        float4 v = *reinterpret_cast<float4*>(stage + lane * STG_STRIDE + c4 * 4);
        yt[c4 * 2 + 0] = __fdividef(v.x, v.y);
        yt[c4 * 2 + 1] = __fdividef(v.z, v.w);
    }
#pragma unroll
    for (int t = 0; t < 8; t++) {
        float4 sq = *reinterpret_cast<const float4*>(g_sigQ + sqbase + t * 4);
        float4 ov;
        ov.x = sq.x * yt[t * 4 + 0];
        ov.y = sq.y * yt[t * 4 + 1];
        ov.z = sq.z * yt[t * 4 + 2];
        ov.w = sq.w * yt[t * 4 + 3];
        *reinterpret_cast<float4*>(g_Yt + sqbase + t * 4) = ov;
    }
}

// ---------------------------------------------------------------------------
// Launch.  Inputs (metadata order):
//  0:x_q 1:x_kv 2:bias 3:wq_w 4:wq_b 5:wk_w 6:wk_b 7:wv_w 8:wv_b 9:f2_w 10:f2_b
// ---------------------------------------------------------------------------
extern "C" void kernel_launch(void* const* d_in, const int* in_sizes, int n_in,
                              void* d_out, int out_size) {
    (void)in_sizes; (void)n_in; (void)out_size;
    const float* x_q  = (const float*)d_in[0];
    const float* x_kv = (const float*)d_in[1];
    const float* bias = (const float*)d_in[2];
    const float* wq_w = (const float*)d_in[3];
    const float* wq_b = (const float*)d_in[4];
    const float* wk_w = (const float*)d_in[5];
    const float* wk_b = (const float*)d_in[6];
    const float* wv_w = (const float*)d_in[7];
    const float* wv_b = (const float*)d_in[8];
    const float* f2_w = (const float*)d_in[9];
    const float* f2_b = (const float*)d_in[10];
    float* out = (float*)d_out;

    float *p_wkv, *p_sigQ, *p_Yt;
    __half *p_kvi;
    cudaGetSymbolAddress((void**)&p_wkv,  g_wkv);
    cudaGetSymbolAddress((void**)&p_sigQ, g_sigQ);
    cudaGetSymbolAddress((void**)&p_Yt,   g_Yt);
    cudaGetSymbolAddress((void**)&p_kvi,  g_kvi);

    cudaFuncSetAttribute((const void*)gemm32_kernel<0>,
                         cudaFuncAttributeMaxDynamicSharedMemorySize, SMEM32);
    cudaFuncSetAttribute((const void*)gemm32_kernel<1>,
                         cudaFuncAttributeMaxDynamicSharedMemorySize, SMEM32);
    cudaFuncSetAttribute((const void*)gemm32_kernel<2>,
                         cudaFuncAttributeMaxDynamicSharedMemorySize, SMEM32);
    cudaFuncSetAttribute((const void*)aft16_kernel,
                         cudaFuncAttributeMaxDynamicSharedMemorySize, SMEM16);

    // 0) interleave wk|wv
    prep_wkv_kernel<<<(DKV * HH) / 256, 256>>>(wk_w, wv_w);
    // 1) exp(bias) -> fp16
    {
        size_t n8 = ((size_t)BATCH * NQ * NKV) / 8;
        exp_bias_h_kernel<<<(unsigned)(n8 / 256), 256>>>(bias);
    }
    // 2) sigQ = sigmoid(x_q @ wq_w + wq_b)
    {
        dim3 grid((BATCH * NQ) / 128, HH / 128);
        gemm32_kernel<0><<<grid, 256, SMEM32>>>(
            x_q, DQ, wq_w, HH, DQ, wq_b, nullptr, p_sigQ, nullptr, HH);
    }
    // 3) kvi = interleaved (ekv, expK) fp16 via single N=512 GEMM
    {
        dim3 grid((BATCH * NKV) / 128, NI / 128);
        gemm32_kernel<1><<<grid, 256, SMEM32>>>(
            x_kv, DKV, p_wkv, NI, DKV, wk_b, wv_b, nullptr, p_kvi, NI);
    }
    // 4) AFT core (fp16 tensor)
    {
        dim3 grid(NQ / 128, NI / 128, BATCH);
        aft16_kernel<<<grid, 256, SMEM16>>>();
    }
    // 5) out = Yt @ f2_w + f2_b
    {
        dim3 grid((BATCH * NQ) / 128, HH / 128);
        gemm32_kernel<2><<<grid, 256, SMEM32>>>(
            p_Yt, HH, f2_w, HH, HH, f2_b, nullptr, out, nullptr, HH);
    }
}

// round 6
// speedup vs baseline: 2.9952x; 1.7877x over previous
#include <cuda_runtime.h>
#include <cuda_fp16.h>
#include <mma.h>
#include <cstdint>

using namespace nvcuda;

// Problem dims (fixed)
#define BATCH 8
#define NQ    2048
#define NKV   2048
#define DQ    1024
#define DKV   1024
#define HH    256
#define NI    512            // interleaved (num,den) width

// Scratch (device globals — no allocation allowed)
__device__ __half g_expwh[(size_t)BATCH * NQ * NKV]; // fp16 exp(bias)       67 MB
__device__ __half g_xqh [BATCH * NQ * DQ];           // fp16 x_q             33.5 MB
__device__ __half g_xkvh[BATCH * NKV * DKV];         // fp16 x_kv            33.5 MB
__device__ __half g_wqh [DQ * HH];                   // fp16 wq              0.5 MB
__device__ __half g_wkvh[DKV * NI];                  // fp16 interleaved wk|wv 1 MB
__device__ __half g_kvi [BATCH * NKV * NI];          // interleaved ekv/expK 16.8 MB
__device__ float  g_sigQ[BATCH * NQ * HH];           // sigmoid(Q)           16.8 MB
__device__ float  g_Yt  [BATCH * NQ * HH];           // sig(Q)*num/den       16.8 MB

__device__ __forceinline__ void cp16(uint32_t saddr, const void* gptr) {
    asm volatile("cp.async.cg.shared.global [%0], [%1], 16;" :: "r"(saddr), "l"(gptr));
}
#define CP_COMMIT() asm volatile("cp.async.commit_group;" ::: "memory")
#define CP_WAIT1()  asm volatile("cp.async.wait_group 1;" ::: "memory")
#define CP_WAIT0()  asm volatile("cp.async.wait_group 0;" ::: "memory")

// ---------------------------------------------------------------------------
// Elementwise prep kernels
// ---------------------------------------------------------------------------
__global__ __launch_bounds__(256) void cvt_f2h_kernel(
    const float* __restrict__ in, __half* __restrict__ out)
{
    size_t i = (size_t)blockIdx.x * 256 + threadIdx.x;  // 8 elems / thread
    float4 a = reinterpret_cast<const float4*>(in)[2 * i];
    float4 b = reinterpret_cast<const float4*>(in)[2 * i + 1];
    __half2 h[4];
    h[0] = __floats2half2_rn(a.x, a.y);
    h[1] = __floats2half2_rn(a.z, a.w);
    h[2] = __floats2half2_rn(b.x, b.y);
    h[3] = __floats2half2_rn(b.z, b.w);
    reinterpret_cast<uint4*>(out)[i] = *reinterpret_cast<uint4*>(h);
}

__global__ __launch_bounds__(256) void prep_wkv_h_kernel(
    const float* __restrict__ wk, const float* __restrict__ wv)
{
    int idx = blockIdx.x * 256 + threadIdx.x;   // k*256 + j
    reinterpret_cast<__half2*>(g_wkvh)[idx] = __floats2half2_rn(wk[idx], wv[idx]);
}

__global__ __launch_bounds__(256) void exp_bias_h_kernel(const float* __restrict__ bias) {
    size_t i = (size_t)blockIdx.x * 256 + threadIdx.x;  // 8 elems / thread
    float4 a = reinterpret_cast<const float4*>(bias)[2 * i];
    float4 b = reinterpret_cast<const float4*>(bias)[2 * i + 1];
    __half2 h[4];
    h[0] = __floats2half2_rn(__expf(a.x), __expf(a.y));
    h[1] = __floats2half2_rn(__expf(a.z), __expf(a.w));
    h[2] = __floats2half2_rn(__expf(b.x), __expf(b.y));
    h[3] = __floats2half2_rn(__expf(b.z), __expf(b.w));
    reinterpret_cast<uint4*>(g_expwh)[i] = *reinterpret_cast<uint4*>(h);
}

// ===========================================================================
// fp16 GEMM template: BM=128 BN=128 BK=64, m16n16k16, 8 warps (4x2),
// 3-stage cp.async pipeline. Row-major A [M,K], row-major B [K,N].
// Grid: (N/128, M/128, batch)
// EPI: 0 = Of = sigmoid(x + v0[col])
//      1 = pairwise (K,V) -> Oh interleaved fp16 (ekv, expK)
//      2 = AFT: Of = aux * num/den from adjacent (even,odd) cols
// ===========================================================================
#define HA_STRIDE 72
#define HB_STRIDE 136
#define HSTAGE    (128 * HA_STRIDE + 64 * HB_STRIDE)   // 17920 halves
#define SMEM16    (3 * HSTAGE * 2)                     // 107520 B
#define STG_STRIDE 68
#define STG_WARP   (32 * STG_STRIDE)

template<int EPI>
__global__ __launch_bounds__(256) void gemm16_kernel(
    const __half* __restrict__ A, int lda, unsigned long long sAz,
    const __half* __restrict__ Bg, int ldb, unsigned long long sBz, int Ktot,
    const float* __restrict__ v0, const float* __restrict__ v1,
    const float* __restrict__ aux, unsigned long long sXz,
    float* __restrict__ Of, __half* __restrict__ Oh, int ldo,
    unsigned long long sOz)
{
    extern __shared__ __align__(16) float smf[];
    __half* sm = reinterpret_cast<__half*>(smf);
    const int tid = threadIdx.x, wid = tid >> 5, lane = tid & 31;
    const int n0 = blockIdx.x * 128, m0 = blockIdx.y * 128;
    const int z = blockIdx.z;
    const int wm = wid >> 1, wn = wid & 1;

    const __half* Ab = A + (size_t)z * sAz + (size_t)m0 * lda;
    const __half* Bb = Bg + (size_t)z * sBz;

    using FA = wmma::fragment<wmma::matrix_a, 16, 16, 16, __half, wmma::row_major>;
    using FB = wmma::fragment<wmma::matrix_b, 16, 16, 16, __half, wmma::row_major>;
    using FC = wmma::fragment<wmma::accumulator, 16, 16, 16, float>;

    FC acc[2][4];
#pragma unroll
    for (int mi = 0; mi < 2; mi++)
#pragma unroll
        for (int ni = 0; ni < 4; ni++)
            wmma::fill_fragment(acc[mi][ni], 0.0f);

    auto load = [&](int c) {
        __half* base = sm + (c % 3) * HSTAGE;
        const int k0 = c * 64;
#pragma unroll
        for (int i = 0; i < 4; i++) {       // A: 128x64 halves
            int idx = tid + i * 256;
            int r = idx >> 3, c8 = idx & 7;
            cp16((uint32_t)__cvta_generic_to_shared(base + r * HA_STRIDE + c8 * 8),
                 Ab + (size_t)r * lda + k0 + c8 * 8);
        }
#pragma unroll
        for (int i = 0; i < 4; i++) {       // B: 64x128 halves
            int idx = tid + i * 256;
            int r = idx >> 4, c8 = idx & 15;
            cp16((uint32_t)__cvta_generic_to_shared(
                     base + 128 * HA_STRIDE + r * HB_STRIDE + c8 * 8),
                 Bb + (size_t)(k0 + r) * ldb + n0 + c8 * 8);
        }
        CP_COMMIT();
    };

    const int nchunk = Ktot / 64;
    load(0);
    load(1);

    for (int c = 0; c < nchunk; c++) {
        if (c + 1 < nchunk) CP_WAIT1(); else CP_WAIT0();
        __syncthreads();
        if (c + 2 < nchunk) load(c + 2);

        __half* Abase = sm + (c % 3) * HSTAGE;
        __half* Bbase = Abase + 128 * HA_STRIDE;
#pragma unroll
        for (int kk = 0; kk < 4; kk++) {
            FA a[2];
#pragma unroll
            for (int mi = 0; mi < 2; mi++)
                wmma::load_matrix_sync(a[mi],
                    Abase + (wm * 32 + mi * 16) * HA_STRIDE + kk * 16, HA_STRIDE);
#pragma unroll
            for (int ni = 0; ni < 4; ni++) {
                FB b;
                wmma::load_matrix_sync(b,
                    Bbase + kk * 16 * HB_STRIDE + wn * 64 + ni * 16, HB_STRIDE);
#pragma unroll
                for (int mi = 0; mi < 2; mi++)
                    wmma::mma_sync(acc[mi][ni], a[mi], b, acc[mi][ni]);
            }
        }
    }

    // ---- Epilogue: per-warp smem staging ----
    __syncthreads();
    float* stage = smf + wid * STG_WARP;
#pragma unroll
    for (int mi = 0; mi < 2; mi++)
#pragma unroll
        for (int ni = 0; ni < 4; ni++)
            wmma::store_matrix_sync(stage + mi * 16 * STG_STRIDE + ni * 16,
                                    acc[mi][ni], STG_STRIDE, wmma::mem_row_major);
    __syncwarp();

    const int grow  = m0 + wm * 32 + lane;
    const int gcolb = n0 + wn * 64;

    if (EPI == 2) {
        // AFT epilogue: adjacent (even=num, odd=den) pairs -> 32 h values
        const int hb = gcolb >> 1;
        const size_t sqbase = (size_t)z * sXz + (size_t)grow * HH + hb;
        float yt[32];
#pragma unroll
        for (int c4 = 0; c4 < 16; c4++) {
            float4 v = *reinterpret_cast<float4*>(stage + lane * STG_STRIDE + c4 * 4);
            yt[c4 * 2 + 0] = __fdividef(v.x, v.y);
            yt[c4 * 2 + 1] = __fdividef(v.z, v.w);
        }
#pragma unroll
        for (int t = 0; t < 8; t++) {
            float4 sq = *reinterpret_cast<const float4*>(aux + sqbase + t * 4);
            float4 ov;
            ov.x = sq.x * yt[t * 4 + 0];
            ov.y = sq.y * yt[t * 4 + 1];
            ov.z = sq.z * yt[t * 4 + 2];
            ov.w = sq.w * yt[t * 4 + 3];
            *reinterpret_cast<float4*>(Of + (size_t)z * sOz + (size_t)grow * HH + hb + t * 4) = ov;
        }
    } else {
#pragma unroll
        for (int c4 = 0; c4 < 16; c4++) {
            float4 v = *reinterpret_cast<float4*>(stage + lane * STG_STRIDE + c4 * 4);
            int gc = gcolb + c4 * 4;
            if (EPI == 0) {
                float4 bv = *reinterpret_cast<const float4*>(v0 + gc);
                float4 ov;
                ov.x = 1.0f / (1.0f + __expf(-(v.x + bv.x)));
                ov.y = 1.0f / (1.0f + __expf(-(v.y + bv.y)));
                ov.z = 1.0f / (1.0f + __expf(-(v.z + bv.z)));
                ov.w = 1.0f / (1.0f + __expf(-(v.w + bv.w)));
                *reinterpret_cast<float4*>(Of + (size_t)z * sOz + (size_t)grow * ldo + gc) = ov;
            } else {  // EPI == 1: (v.x=K_j, v.y=V_j, v.z=K_{j+1}, v.w=V_{j+1})
                int j = gc >> 1;
                float ek0 = __expf(v.x + v0[j]);
                float kv0 = ek0 * (v.y + v1[j]);
                float ek1 = __expf(v.z + v0[j + 1]);
                float kv1 = ek1 * (v.w + v1[j + 1]);
                __half2* po = reinterpret_cast<__half2*>(Oh + (size_t)z * sOz + (size_t)grow * ldo + gc);
                po[0] = __floats2half2_rn(kv0, ek0);   // cols (2j, 2j+1) = (ekv, expK)
                po[1] = __floats2half2_rn(kv1, ek1);
            }
        }
    }
}

// ===========================================================================
// tf32 GEMM (kept for the small output projection, preserves precision)
// ===========================================================================
#define SA_STRIDE 36
#define SB_STRIDE 136
#define STAGE_F   (128 * SA_STRIDE + 32 * SB_STRIDE)   // 8960 floats
#define SMEM32    (3 * STAGE_F * 4)                    // 107520 B

__global__ __launch_bounds__(256) void outproj32_kernel(
    const float* __restrict__ A, int lda,
    const float* __restrict__ Bg, int ldb, int Ktot,
    const float* __restrict__ v0, float* __restrict__ Of, int ldo)
{
    extern __shared__ __align__(16) float sm[];
    const int tid = threadIdx.x, wid = tid >> 5, lane = tid & 31;
    const int n0 = blockIdx.x * 128, m0 = blockIdx.y * 128;
    const int wm = wid >> 1, wn = wid & 1;
    const float* Ab = A + (size_t)m0 * lda;

    using FA = wmma::fragment<wmma::matrix_a, 16, 16, 8, wmma::precision::tf32, wmma::row_major>;
    using FB = wmma::fragment<wmma::matrix_b, 16, 16, 8, wmma::precision::tf32, wmma::row_major>;
    using FC = wmma::fragment<wmma::accumulator, 16, 16, 8, float>;

    FC acc[2][4];
#pragma unroll
    for (int mi = 0; mi < 2; mi++)
#pragma unroll
        for (int ni = 0; ni < 4; ni++)
            wmma::fill_fragment(acc[mi][ni], 0.0f);

    auto load = [&](int c) {
        float* base = sm + (c % 3) * STAGE_F;
        const int k0 = c * 32;
#pragma unroll
        for (int i = 0; i < 4; i++) {
            int idx = tid + i * 256;
            int r = idx >> 3, c4 = idx & 7;
            cp16((uint32_t)__cvta_generic_to_shared(base + r * SA_STRIDE + c4 * 4),
                 Ab + (size_t)r * lda + k0 + c4 * 4);
        }
#pragma unroll
        for (int i = 0; i < 4; i++) {
            int idx = tid + i * 256;
            int r = idx >> 5, c4 = idx & 31;
            cp16((uint32_t)__cvta_generic_to_shared(
                     base + 128 * SA_STRIDE + r * SB_STRIDE + c4 * 4),
                 Bg + (size_t)(k0 + r) * ldb + n0 + c4 * 4);
        }
        CP_COMMIT();
    };

    const int nchunk = Ktot / 32;
    load(0);
    load(1);

    for (int c = 0; c < nchunk; c++) {
        if (c + 1 < nchunk) CP_WAIT1(); else CP_WAIT0();
        __syncthreads();
        if (c + 2 < nchunk) load(c + 2);

        float* Abase = sm + (c % 3) * STAGE_F;
        float* Bbase = Abase + 128 * SA_STRIDE;
#pragma unroll
        for (int kk = 0; kk < 4; kk++) {
            FA a[2];
#pragma unroll
            for (int mi = 0; mi < 2; mi++) {
                wmma::load_matrix_sync(a[mi],
                    Abase + (wm * 32 + mi * 16) * SA_STRIDE + kk * 8, SA_STRIDE);
#pragma unroll
                for (int e = 0; e < a[mi].num_elements; e++)
                    a[mi].x[e] = wmma::__float_to_tf32(a[mi].x[e]);
            }
#pragma unroll
            for (int ni = 0; ni < 4; ni++) {
                FB b;
                wmma::load_matrix_sync(b,
                    Bbase + kk * 8 * SB_STRIDE + wn * 64 + ni * 16, SB_STRIDE);
#pragma unroll
                for (int e = 0; e < b.num_elements; e++)
                    b.x[e] = wmma::__float_to_tf32(b.x[e]);
#pragma unroll
                for (int mi = 0; mi < 2; mi++)
                    wmma::mma_sync(acc[mi][ni], a[mi], b, acc[mi][ni]);
            }
        }
    }

    __syncthreads();
    float* stage = sm + wid * STG_WARP;
#pragma unroll
    for (int mi = 0; mi < 2; mi++)
#pragma unroll
        for (int ni = 0; ni < 4; ni++)
            wmma::store_matrix_sync(stage + mi * 16 * STG_STRIDE + ni * 16,
                                    acc[mi][ni], STG_STRIDE, wmma::mem_row_major);
    __syncwarp();

    const int grow  = m0 + wm * 32 + lane;
    const int gcolb = n0 + wn * 64;
#pragma unroll
    for (int c4 = 0; c4 < 16; c4++) {
        float4 v = *reinterpret_cast<float4*>(stage + lane * STG_STRIDE + c4 * 4);
        int gc = gcolb + c4 * 4;
        float4 bv = *reinterpret_cast<const float4*>(v0 + gc);
        float4 ov;
        ov.x = v.x + bv.x; ov.y = v.y + bv.y;
        ov.z = v.z + bv.z; ov.w = v.w + bv.w;
        *reinterpret_cast<float4*>(Of + (size_t)grow * ldo + gc) = ov;
    }
}

// ---------------------------------------------------------------------------
// Launch.  Inputs (metadata order):
//  0:x_q 1:x_kv 2:bias 3:wq_w 4:wq_b 5:wk_w 6:wk_b 7:wv_w 8:wv_b 9:f2_w 10:f2_b
// ---------------------------------------------------------------------------
extern "C" void kernel_launch(void* const* d_in, const int* in_sizes, int n_in,
                              void* d_out, int out_size) {
    (void)in_sizes; (void)n_in; (void)out_size;
    const float* x_q  = (const float*)d_in[0];
    const float* x_kv = (const float*)d_in[1];
    const float* bias = (const float*)d_in[2];
    const float* wq_w = (const float*)d_in[3];
    const float* wq_b = (const float*)d_in[4];
    const float* wk_w = (const float*)d_in[5];
    const float* wk_b = (const float*)d_in[6];
    const float* wv_w = (const float*)d_in[7];
    const float* wv_b = (const float*)d_in[8];
    const float* f2_w = (const float*)d_in[9];
    const float* f2_b = (const float*)d_in[10];
    float* out = (float*)d_out;

    __half *p_expwh, *p_xqh, *p_xkvh, *p_wqh, *p_wkvh, *p_kvi;
    float *p_sigQ, *p_Yt;
    cudaGetSymbolAddress((void**)&p_expwh, g_expwh);
    cudaGetSymbolAddress((void**)&p_xqh,   g_xqh);
    cudaGetSymbolAddress((void**)&p_xkvh,  g_xkvh);
    cudaGetSymbolAddress((void**)&p_wqh,   g_wqh);
    cudaGetSymbolAddress((void**)&p_wkvh,  g_wkvh);
    cudaGetSymbolAddress((void**)&p_kvi,   g_kvi);
    cudaGetSymbolAddress((void**)&p_sigQ,  g_sigQ);
    cudaGetSymbolAddress((void**)&p_Yt,    g_Yt);

    cudaFuncSetAttribute((const void*)gemm16_kernel<0>,
                         cudaFuncAttributeMaxDynamicSharedMemorySize, SMEM16);
    cudaFuncSetAttribute((const void*)gemm16_kernel<1>,
                         cudaFuncAttributeMaxDynamicSharedMemorySize, SMEM16);
    cudaFuncSetAttribute((const void*)gemm16_kernel<2>,
                         cudaFuncAttributeMaxDynamicSharedMemorySize, SMEM16);
    cudaFuncSetAttribute((const void*)outproj32_kernel,
                         cudaFuncAttributeMaxDynamicSharedMemorySize, SMEM32);

    // 0) conversions
    cvt_f2h_kernel<<<(BATCH * NQ * DQ) / 8 / 256, 256>>>(x_q, p_xqh);
    cvt_f2h_kernel<<<(BATCH * NKV * DKV) / 8 / 256, 256>>>(x_kv, p_xkvh);
    cvt_f2h_kernel<<<(DQ * HH) / 8 / 256, 256>>>(wq_w, p_wqh);
    prep_wkv_h_kernel<<<(DKV * HH) / 256, 256>>>(wk_w, wv_w);
    {
        size_t n8 = ((size_t)BATCH * NQ * NKV) / 8;
        exp_bias_h_kernel<<<(unsigned)(n8 / 256), 256>>>(bias);
    }
    // 1) sigQ = sigmoid(x_q @ wq + bq)   [fp16 GEMM, N=256]
    {
        dim3 grid(HH / 128, (BATCH * NQ) / 128, 1);
        gemm16_kernel<0><<<grid, 256, SMEM16>>>(
            p_xqh, DQ, 0ull, p_wqh, HH, 0ull, DQ,
            wq_b, nullptr, nullptr, 0ull, p_sigQ, nullptr, HH, 0ull);
    }
    // 2) kvi = interleaved (ekv, expK)   [fp16 GEMM, N=512]
    {
        dim3 grid(NI / 128, (BATCH * NKV) / 128, 1);
        gemm16_kernel<1><<<grid, 256, SMEM16>>>(
            p_xkvh, DKV, 0ull, p_wkvh, NI, 0ull, DKV,
            wk_b, wv_b, nullptr, 0ull, nullptr, p_kvi, NI, 0ull);
    }
    // 3) AFT core: Yt = sigQ * num/den  [fp16 GEMM, batched]
    {
        dim3 grid(NI / 128, NQ / 128, BATCH);
        gemm16_kernel<2><<<grid, 256, SMEM16>>>(
            p_expwh, NKV, (unsigned long long)NQ * NKV,
            p_kvi, NI, (unsigned long long)NKV * NI, NKV,
            nullptr, nullptr, p_sigQ, (unsigned long long)NQ * HH,
            p_Yt, nullptr, NI, (unsigned long long)NQ * HH);
    }
    // 4) out = Yt @ f2_w + f2_b          [tf32, preserves precision]
    {
        dim3 grid(HH / 128, (BATCH * NQ) / 128, 1);
        outproj32_kernel<<<grid, 256, SMEM32>>>(
            p_Yt, HH, f2_w, HH, HH, f2_b, out, HH);
    }
}